// round 14
// baseline (speedup 1.0000x reference)
#include <cuda_runtime.h>
#include <cuda_bf16.h>
#include <cstdint>

#define NN 100000
#define NE 1600000
#define OUT_DECE (NN)
#define OUT_POS  (NN + NE)
#define OUT_VEL  (NN + NE + NN)

// ---------------- device-global scratch ----------------
__device__ float4 g_agg[2 * NN];
__device__ float  g_prep[40];
// split bf16 weights: [l][n(32)][k(64)]: k<32 = hi(W[k][n]), k>=32 = lo residual
__device__ __align__(16) unsigned short g_wcat[2 * 32 * 64];

// ---------------- RK coefficients (H=0.1 absorbed, rebased on yn) ----------------
#define C_B1   ((float)(0.1 * (35.0/384.0)))
#define C_B3   ((float)(0.1 * (500.0/1113.0)))
#define C_B4   ((float)(0.1 * (125.0/192.0)))
#define C_B5   ((float)(0.1 * (-2187.0/6784.0)))
#define C_B6   ((float)(0.1 * (11.0/84.0)))
#define C_R1   ((float)(0.1 * (1.0/5.0 - 35.0/384.0)))
#define C_S31  ((float)(0.1 * (3.0/40.0 - 35.0/384.0)))
#define C_R2   ((float)(0.1 * (9.0/40.0)))
#define C_S41  ((float)(0.1 * (44.0/45.0 - 35.0/384.0)))
#define C_S42  ((float)(0.1 * (-56.0/15.0)))
#define C_R3   ((float)(0.1 * (32.0/9.0 - 500.0/1113.0)))
#define C_S51  ((float)(0.1 * (19372.0/6561.0 - 35.0/384.0)))
#define C_S52  ((float)(0.1 * (-25360.0/2187.0)))
#define C_S53  ((float)(0.1 * (64448.0/6561.0 - 500.0/1113.0)))
#define C_R4   ((float)(0.1 * (-212.0/729.0 - 125.0/192.0)))
#define C_S61  ((float)(0.1 * (9017.0/3168.0 - 35.0/384.0)))
#define C_S62  ((float)(0.1 * (-355.0/33.0)))
#define C_S63  ((float)(0.1 * (46732.0/5247.0 - 500.0/1113.0)))
#define C_S64  ((float)(0.1 * (49.0/176.0 - 125.0/192.0)))
#define C_R5   ((float)(0.1 * (-5103.0/18656.0 + 2187.0/6784.0)))

// ---------------- helpers ----------------
// pack (lo, hi) floats -> bf16x2 (first arg in low 16 bits)
__device__ __forceinline__ uint32_t pkbf(float lo, float hi) {
    uint32_t r;
    asm("cvt.rn.bf16x2.f32 %0, %1, %2;" : "=r"(r) : "f"(hi), "f"(lo));
    return r;
}
__device__ __forceinline__ void mma16816(float d[4], const uint32_t a[4], const uint32_t b[2]) {
    asm volatile("mma.sync.aligned.m16n8k16.row.col.f32.bf16.bf16.f32 "
                 "{%0,%1,%2,%3}, {%4,%5,%6,%7}, {%8,%9}, {%0,%1,%2,%3};"
                 : "+f"(d[0]), "+f"(d[1]), "+f"(d[2]), "+f"(d[3])
                 : "r"(a[0]), "r"(a[1]), "r"(a[2]), "r"(a[3]), "r"(b[0]), "r"(b[1]));
}

// ---------------- precompute kernel ----------------
__global__ void prep_kernel(const float* __restrict__ eW, const float* __restrict__ eb,
                            const float* __restrict__ decEW, const float* __restrict__ decEb,
                            const float* __restrict__ noW, const float* __restrict__ nob,
                            const float* __restrict__ decNW, const float* __restrict__ decNb,
                            const float* __restrict__ odeW1, const float* __restrict__ odeW2) {
    int t = threadIdx.x;   // 128
    if (t < 3) {
        float s = 0.f;
        for (int c = 0; c < 10; c++) s += eW[t * 10 + c] * decEW[c];
        g_prep[t] = s;
    } else if (t == 3) {
        float s = decEb[0];
        for (int c = 0; c < 10; c++) s += eb[c] * decEW[c];
        g_prep[3] = s;
    } else if (t >= 4 && t < 36) {
        int j = t - 4;
        float s = 0.f;
        for (int c = 0; c < 10; c++) s += noW[j * 10 + c] * decNW[c];
        g_prep[t] = s;
    } else if (t == 36) {
        float s = decNb[0];
        for (int c = 0; c < 10; c++) s += nob[c] * decNW[c];
        g_prep[36] = s;
    }
    if (t < 64) {
        int l = t >> 5, n = t & 31;
        const float* W = l ? odeW2 : odeW1;
        unsigned short* dst = &g_wcat[l * 2048 + n * 64];
        for (int kk = 0; kk < 32; kk++) {
            float f = W[kk * 32 + n];
            __nv_bfloat16 hi = __float2bfloat16(f);
            __nv_bfloat16 lo = __float2bfloat16(f - __bfloat162float(hi));
            dst[kk]      = __bfloat16_as_ushort(hi);
            dst[32 + kk] = __bfloat16_as_ushort(lo);
        }
    }
}

__global__ void zero_kernel() {
    int i = blockIdx.x * blockDim.x + threadIdx.x;
    if (i < 2 * NN) g_agg[i] = make_float4(0.f, 0.f, 0.f, 0.f);
}

// ---------------- edge kernel ----------------
__global__ void edge_kernel(const float* __restrict__ edges,
                            const int* __restrict__ senders,
                            const int* __restrict__ receivers,
                            float* __restrict__ out) {
    int e = blockIdx.x * blockDim.x + threadIdx.x;
    if (e >= NE) return;
    float e0 = edges[3 * e + 0];
    float e1 = edges[3 * e + 1];
    float e2 = edges[3 * e + 2];
    int s = senders[e];
    int r = receivers[e];
    float c0 = g_prep[0], c1 = g_prep[1], c2 = g_prep[2], d = g_prep[3];
    out[OUT_DECE + e] = fmaf(e0, c0, fmaf(e1, c1, fmaf(e2, c2, d)));
    float4* ps = &g_agg[s];
    float4* pr = &g_agg[NN + r];
    asm volatile("red.global.add.v4.f32 [%0], {%1, %2, %3, %4};"
                 :: "l"(ps), "f"(e0), "f"(e1), "f"(e2), "f"(1.0f) : "memory");
    asm volatile("red.global.add.v4.f32 [%0], {%1, %2, %3, %4};"
                 :: "l"(pr), "f"(e0), "f"(e1), "f"(e2), "f"(1.0f) : "memory");
}

// ---------------- smem: bias table (256B) + k1..k4 thread-private slots ----------
#define SM_BIAS 0
#define SM_K1   256
#define SM_K2   (SM_K1 + 8192)
#define SM_K3   (SM_K2 + 8192)
#define SM_K4   (SM_K3 + 8192)
#define SM_TOTAL (SM_K4 + 8192)   /* 33 KB */

// Build bf16 hi/lo A-fragments from fp32 value fragments (one 16-row m-tile).
__device__ __forceinline__ void mkfrag(const float (&v)[4][4],
                                       uint32_t (&ah)[2][4], uint32_t (&al)[2][4]) {
#pragma unroll
    for (int kt = 0; kt < 2; kt++)
#pragma unroll
        for (int j = 0; j < 4; j++) {
            int nt = 2 * kt + (j >> 1);
            int b = (j & 1) * 2;
            float x = v[nt][b], y = v[nt][b + 1];
            uint32_t hp = pkbf(x, y);
            float r0 = x - __uint_as_float(hp << 16);
            float r1 = y - __uint_as_float(hp & 0xFFFF0000u);
            ah[kt][j] = hp;
            al[kt][j] = pkbf(r0, r1);
        }
}

// fully register-resident f-eval, split accumulator chains (3+3 deep):
// d[nt] = bias + ah0*w0 + ah1*w1 + ah0*w2 ; e[nt] = ah1*w3 + al0*w0 + al1*w1 ; d += e
__device__ __forceinline__ void feval_reg(const float (&v)[4][4],
                                          const uint32_t (&bw)[2][4][4][2],
                                          const float2* __restrict__ sbias, int q,
                                          float (&kv)[4][4]) {
    uint32_t ah[2][4], al[2][4];
    mkfrag(v, ah, al);
    float d[4][4], e[4][4];
#pragma unroll
    for (int nt = 0; nt < 4; nt++) {
        float2 bb = sbias[(0 * 4 + nt) * 4 + q];
        d[nt][0] = bb.x; d[nt][1] = bb.y; d[nt][2] = bb.x; d[nt][3] = bb.y;
        e[nt][0] = 0.f; e[nt][1] = 0.f; e[nt][2] = 0.f; e[nt][3] = 0.f;
        mma16816(d[nt], ah[0], bw[0][0][nt]);   // hi * Whi (k0)
        mma16816(e[nt], ah[1], bw[0][3][nt]);   // hi * Wlo (k1)
        mma16816(d[nt], ah[1], bw[0][1][nt]);   // hi * Whi (k1)
        mma16816(e[nt], al[0], bw[0][0][nt]);   // lo * Whi (k0)
        mma16816(d[nt], ah[0], bw[0][2][nt]);   // hi * Wlo (k0)
        mma16816(e[nt], al[1], bw[0][1][nt]);   // lo * Whi (k1)
    }
#pragma unroll
    for (int nt = 0; nt < 4; nt++)
#pragma unroll
        for (int ii = 0; ii < 4; ii++) d[nt][ii] = fmaxf(d[nt][ii] + e[nt][ii], 0.f);
    mkfrag(d, ah, al);
#pragma unroll
    for (int nt = 0; nt < 4; nt++) {
        float2 bb = sbias[(1 * 4 + nt) * 4 + q];
        kv[nt][0] = bb.x; kv[nt][1] = bb.y; kv[nt][2] = bb.x; kv[nt][3] = bb.y;
        e[nt][0] = 0.f; e[nt][1] = 0.f; e[nt][2] = 0.f; e[nt][3] = 0.f;
        mma16816(kv[nt], ah[0], bw[1][0][nt]);
        mma16816(e[nt],  ah[1], bw[1][3][nt]);
        mma16816(kv[nt], ah[1], bw[1][1][nt]);
        mma16816(e[nt],  al[0], bw[1][0][nt]);
        mma16816(kv[nt], ah[0], bw[1][2][nt]);
        mma16816(e[nt],  al[1], bw[1][1][nt]);
    }
#pragma unroll
    for (int nt = 0; nt < 4; nt++)
#pragma unroll
        for (int ii = 0; ii < 4; ii++) kv[nt][ii] += e[nt][ii];
}

// RK stage frame
#define RK_FRAME(BODY)                                                        \
    {                                                                         \
        float kv[4][4];                                                       \
        feval_reg(v, bw, sbias, q, kv);                                       \
        _Pragma("unroll")                                                     \
        for (int nt = 0; nt < 4; nt++)                                        \
        _Pragma("unroll")                                                     \
        for (int ii = 0; ii < 4; ii++) {                                      \
            int cg = (nt * 4 + ii) * 128 + t;                                 \
            float k = kv[nt][ii];                                             \
            float Y = yn[nt][ii];                                             \
            float uu;                                                         \
            BODY                                                              \
            yn[nt][ii] = Y;                                                   \
            v[nt][ii] = uu;                                                   \
        }                                                                     \
    }

__global__ __launch_bounds__(128, 3)
void ode_kernel(const float* __restrict__ nodes, const float* __restrict__ gl,
                const float* __restrict__ encNW, const float* __restrict__ encNb,
                const float* __restrict__ encEW, const float* __restrict__ encEb,
                const float* __restrict__ b1g, const float* __restrict__ b2g,
                float* __restrict__ out) {
    extern __shared__ char sm[];
    int t = threadIdx.x;
    int w = t >> 5, lane = t & 31;
    int g = lane >> 2, q = lane & 3;
    int rb = w * 16;                    // warp owns 16 local rows
    int cbase = blockIdx.x * 64;        // CTA owns 64 nodes

    // ---- register-stationary B fragments ----
    uint32_t bw[2][4][4][2];
#pragma unroll
    for (int l = 0; l < 2; l++)
#pragma unroll
        for (int k8 = 0; k8 < 4; k8++)
#pragma unroll
            for (int nt = 0; nt < 4; nt++) {
                int n = nt * 8 + g;
                const unsigned short* src = g_wcat + l * 2048 + n * 64 + k8 * 16 + 2 * q;
                bw[l][k8][nt][0] = *(const uint32_t*)(src);
                bw[l][k8][nt][1] = *(const uint32_t*)(src + 8);
            }

    // ---- bias table in smem: [l(2)][nt(4)][q(4)] -> float2 ----
    float2* sbias = (float2*)(sm + SM_BIAS);
    if (t < 32) {
        int l = t >> 4, nt = (t >> 2) & 3, qq = t & 3;
        const float* b = l ? b2g : b1g;
        int c = nt * 8 + 2 * qq;
        sbias[t] = make_float2(__ldg(&b[c]), __ldg(&b[c + 1]));
    }

    // ---- encoder: threads 0..63 handle one node each ----
    float* scr = (float*)(sm + SM_K1);   // overlay: [col(32)][node(64)]
    if (t < 64) {
        int i0 = cbase + t;
        int i = (i0 < NN) ? i0 : (NN - 1);
        float2 nd = reinterpret_cast<const float2*>(nodes)[i];
        float4 sa = g_agg[i];
        float4 ra = g_agg[NN + i];
        float u0[32];
#pragma unroll
        for (int c = 0; c < 10; c++) {
            float wn0 = __ldg(&encNW[c]), wn1 = __ldg(&encNW[10 + c]), bn = __ldg(&encNb[c]);
            u0[c] = fmaf(nd.x, wn0, fmaf(nd.y, wn1, bn));
            float we0 = __ldg(&encEW[c]), we1 = __ldg(&encEW[10 + c]);
            float we2 = __ldg(&encEW[20 + c]), web = __ldg(&encEb[c]);
            u0[10 + c] = fmaf(sa.x, we0, fmaf(sa.y, we1, fmaf(sa.z, we2, sa.w * web)));
            u0[20 + c] = fmaf(ra.x, we0, fmaf(ra.y, we1, fmaf(ra.z, we2, ra.w * web)));
        }
        u0[30] = gl[0];
        u0[31] = gl[1];
#pragma unroll
        for (int c = 0; c < 32; c++) scr[c * 64 + t] = u0[c];
    }
    __syncthreads();

    float yn[4][4], v[4][4];
#pragma unroll
    for (int nt = 0; nt < 4; nt++)
#pragma unroll
        for (int ii = 0; ii < 4; ii++) {
            int row = rb + (ii >> 1) * 8 + g;           // local node 0..63
            int col = nt * 8 + 2 * q + (ii & 1);
            float val = scr[col * 64 + row];
            yn[nt][ii] = val;
            v[nt][ii] = val;
        }
    __syncthreads();

    float* k1s = (float*)(sm + SM_K1);
    float* k2s = (float*)(sm + SM_K2);
    float* k3s = (float*)(sm + SM_K3);
    float* k4s = (float*)(sm + SM_K4);

#pragma unroll 1
    for (int st = 0; st < 10; ++st) {
        RK_FRAME({ k1s[cg] = k; Y = fmaf(k, C_B1, Y); uu = fmaf(k, C_R1, Y); })
        RK_FRAME({ k2s[cg] = k; float tv = fmaf(k1s[cg], C_S31, Y); uu = fmaf(k, C_R2, tv); })
        RK_FRAME({ k3s[cg] = k; Y = fmaf(k, C_B3, Y);
                   float tv = fmaf(k1s[cg], C_S41, Y);
                   tv = fmaf(k2s[cg], C_S42, tv);
                   uu = fmaf(k, C_R3, tv); })
        RK_FRAME({ k4s[cg] = k; Y = fmaf(k, C_B4, Y);
                   float tv = fmaf(k1s[cg], C_S51, Y);
                   tv = fmaf(k2s[cg], C_S52, tv);
                   tv = fmaf(k3s[cg], C_S53, tv);
                   uu = fmaf(k, C_R4, tv); })
        RK_FRAME({ Y = fmaf(k, C_B5, Y);
                   float tv = fmaf(k1s[cg], C_S61, Y);
                   tv = fmaf(k2s[cg], C_S62, tv);
                   tv = fmaf(k3s[cg], C_S63, tv);
                   tv = fmaf(k4s[cg], C_S64, tv);
                   uu = fmaf(k, C_R5, tv); })
        RK_FRAME({ Y = fmaf(k, C_B6, Y); uu = Y; })
    }

    // ---- decode + integrator epilogue (frag space, shfl row-reduce) ----
    float qc = __ldg(&g_prep[36]);
    float pdec[4][2];
#pragma unroll
    for (int nt = 0; nt < 4; nt++) {
        int c = nt * 8 + 2 * q;
        pdec[nt][0] = __ldg(&g_prep[4 + c]);
        pdec[nt][1] = __ldg(&g_prep[5 + c]);
    }
    float s1 = 0.f, s2 = 0.f;
#pragma unroll
    for (int nt = 0; nt < 4; nt++) {
        s1 = fmaf(yn[nt][0], pdec[nt][0], fmaf(yn[nt][1], pdec[nt][1], s1));
        s2 = fmaf(yn[nt][2], pdec[nt][0], fmaf(yn[nt][3], pdec[nt][1], s2));
    }
    s1 += __shfl_xor_sync(0xFFFFFFFFu, s1, 1);
    s1 += __shfl_xor_sync(0xFFFFFFFFu, s1, 2);
    s2 += __shfl_xor_sync(0xFFFFFFFFu, s2, 1);
    s2 += __shfl_xor_sync(0xFFFFFFFFu, s2, 2);
    if (q == 0) {
        int iA = cbase + rb + g;
        int iB = iA + 8;
        if (iA < NN) {
            float2 n2 = reinterpret_cast<const float2*>(nodes)[iA];
            float dec = s1 + qc;
            out[iA] = dec;
            float vel = n2.y + dec;
            out[OUT_VEL + iA] = vel;
            out[OUT_POS + iA] = n2.x + vel;
        }
        if (iB < NN) {
            float2 n2 = reinterpret_cast<const float2*>(nodes)[iB];
            float dec = s2 + qc;
            out[iB] = dec;
            float vel = n2.y + dec;
            out[OUT_VEL + iB] = vel;
            out[OUT_POS + iB] = n2.x + vel;
        }
    }
}

extern "C" void kernel_launch(void* const* d_in, const int* in_sizes, int n_in,
                              void* d_out, int out_size) {
    const float* nodes     = (const float*)d_in[0];
    const float* edges     = (const float*)d_in[1];
    const int*   senders   = (const int*)d_in[2];
    const int*   receivers = (const int*)d_in[3];
    const float* globals_  = (const float*)d_in[4];
    const float* encNW     = (const float*)d_in[5];
    const float* encNb     = (const float*)d_in[6];
    const float* encEW     = (const float*)d_in[7];
    const float* encEb     = (const float*)d_in[8];
    const float* odeW1     = (const float*)d_in[9];
    const float* odeb1     = (const float*)d_in[10];
    const float* odeW2     = (const float*)d_in[11];
    const float* odeb2     = (const float*)d_in[12];
    const float* noW       = (const float*)d_in[13];
    const float* nob       = (const float*)d_in[14];
    const float* decNW     = (const float*)d_in[15];
    const float* decNb     = (const float*)d_in[16];
    const float* decEW     = (const float*)d_in[17];
    const float* decEb     = (const float*)d_in[18];
    float* out = (float*)d_out;

    cudaFuncSetAttribute(ode_kernel, cudaFuncAttributeMaxDynamicSharedMemorySize, SM_TOTAL);

    prep_kernel<<<1, 128>>>(encEW, encEb, decEW, decEb, noW, nob, decNW, decNb,
                            odeW1, odeW2);
    zero_kernel<<<(2 * NN + 255) / 256, 256>>>();
    edge_kernel<<<(NE + 255) / 256, 256>>>(edges, senders, receivers, out);
    int nblk = (NN + 63) / 64;
    ode_kernel<<<nblk, 128, SM_TOTAL>>>(nodes, globals_, encNW, encNb, encEW, encEb,
                                        odeb1, odeb2, out);
}

// round 16
// speedup vs baseline: 1.0949x; 1.0949x over previous
#include <cuda_runtime.h>
#include <cuda_bf16.h>
#include <cstdint>

#define NN 100000
#define NE 1600000
#define OUT_DECE (NN)
#define OUT_POS  (NN + NE)
#define OUT_VEL  (NN + NE + NN)

typedef unsigned long long ull;

// ---------------- device-global scratch ----------------
__device__ float4 g_agg[2 * NN];
__device__ float  g_prep[40];
// split bf16 weights: [l][n(32)][k(64)]: k<32 = hi(W[k][n]), k>=32 = lo residual
__device__ __align__(16) unsigned short g_wcat[2 * 32 * 64];

// ---------------- RK coefficients (H=0.1 absorbed, rebased on yn) ----------------
#define C_B1   ((float)(0.1 * (35.0/384.0)))
#define C_B3   ((float)(0.1 * (500.0/1113.0)))
#define C_B4   ((float)(0.1 * (125.0/192.0)))
#define C_B5   ((float)(0.1 * (-2187.0/6784.0)))
#define C_B6   ((float)(0.1 * (11.0/84.0)))
#define C_R1   ((float)(0.1 * (1.0/5.0 - 35.0/384.0)))
#define C_S31  ((float)(0.1 * (3.0/40.0 - 35.0/384.0)))
#define C_R2   ((float)(0.1 * (9.0/40.0)))
#define C_S41  ((float)(0.1 * (44.0/45.0 - 35.0/384.0)))
#define C_S42  ((float)(0.1 * (-56.0/15.0)))
#define C_R3   ((float)(0.1 * (32.0/9.0 - 500.0/1113.0)))
#define C_S51  ((float)(0.1 * (19372.0/6561.0 - 35.0/384.0)))
#define C_S52  ((float)(0.1 * (-25360.0/2187.0)))
#define C_S53  ((float)(0.1 * (64448.0/6561.0 - 500.0/1113.0)))
#define C_R4   ((float)(0.1 * (-212.0/729.0 - 125.0/192.0)))
#define C_S61  ((float)(0.1 * (9017.0/3168.0 - 35.0/384.0)))
#define C_S62  ((float)(0.1 * (-355.0/33.0)))
#define C_S63  ((float)(0.1 * (46732.0/5247.0 - 500.0/1113.0)))
#define C_S64  ((float)(0.1 * (49.0/176.0 - 125.0/192.0)))
#define C_R5   ((float)(0.1 * (-5103.0/18656.0 + 2187.0/6784.0)))

// ---------------- packed helpers ----------------
__device__ __forceinline__ ull pk2(float lo, float hi) {
    ull r;
    asm("mov.b64 %0, {%1, %2};" : "=l"(r) : "r"(__float_as_uint(lo)), "r"(__float_as_uint(hi)));
    return r;
}
__device__ __forceinline__ void upk2(ull v, float& lo, float& hi) {
    unsigned a, b;
    asm("mov.b64 {%0, %1}, %2;" : "=r"(a), "=r"(b) : "l"(v));
    lo = __uint_as_float(a); hi = __uint_as_float(b);
}
__device__ __forceinline__ ull f2fma(ull a, ull b, ull c) {
    ull d;
    asm("fma.rn.f32x2 %0, %1, %2, %3;" : "=l"(d) : "l"(a), "l"(b), "l"(c));
    return d;
}
__device__ __forceinline__ ull cpk(float x) {
    unsigned u = __float_as_uint(x);
    return (((ull)u) << 32) | (ull)u;
}
// pack (lo, hi) floats -> bf16x2 rn (first arg in low 16 bits)
__device__ __forceinline__ uint32_t pkbf(float lo, float hi) {
    uint32_t r;
    asm("cvt.rn.bf16x2.f32 %0, %1, %2;" : "=r"(r) : "f"(hi), "f"(lo));
    return r;
}
__device__ __forceinline__ void mma16816(float d[4], const uint32_t a[4], const uint32_t b[2]) {
    asm volatile("mma.sync.aligned.m16n8k16.row.col.f32.bf16.bf16.f32 "
                 "{%0,%1,%2,%3}, {%4,%5,%6,%7}, {%8,%9}, {%0,%1,%2,%3};"
                 : "+f"(d[0]), "+f"(d[1]), "+f"(d[2]), "+f"(d[3])
                 : "r"(a[0]), "r"(a[1]), "r"(a[2]), "r"(a[3]), "r"(b[0]), "r"(b[1]));
}

// ---------------- fused zero + precompute kernel ----------------
__global__ void zero_prep_kernel(const float* __restrict__ eW, const float* __restrict__ eb,
                                 const float* __restrict__ decEW, const float* __restrict__ decEb,
                                 const float* __restrict__ noW, const float* __restrict__ nob,
                                 const float* __restrict__ decNW, const float* __restrict__ decNb,
                                 const float* __restrict__ odeW1, const float* __restrict__ odeW2) {
    int i = blockIdx.x * blockDim.x + threadIdx.x;
    if (i < 2 * NN) g_agg[i] = make_float4(0.f, 0.f, 0.f, 0.f);
    if (blockIdx.x == 0) {
        int t = threadIdx.x;
        if (t < 3) {
            float s = 0.f;
            for (int c = 0; c < 10; c++) s += eW[t * 10 + c] * decEW[c];
            g_prep[t] = s;
        } else if (t == 3) {
            float s = decEb[0];
            for (int c = 0; c < 10; c++) s += eb[c] * decEW[c];
            g_prep[3] = s;
        } else if (t >= 4 && t < 36) {
            int j = t - 4;
            float s = 0.f;
            for (int c = 0; c < 10; c++) s += noW[j * 10 + c] * decNW[c];
            g_prep[t] = s;
        } else if (t == 36) {
            float s = decNb[0];
            for (int c = 0; c < 10; c++) s += nob[c] * decNW[c];
            g_prep[36] = s;
        }
        if (t >= 64 && t < 128) {
            int tt = t - 64;
            int l = tt >> 5, n = tt & 31;
            const float* W = l ? odeW2 : odeW1;
            unsigned short* dst = &g_wcat[l * 2048 + n * 64];
            for (int kk = 0; kk < 32; kk++) {
                float f = W[kk * 32 + n];
                __nv_bfloat16 hi = __float2bfloat16(f);
                __nv_bfloat16 lo = __float2bfloat16(f - __bfloat162float(hi));
                dst[kk]      = __bfloat16_as_ushort(hi);
                dst[32 + kk] = __bfloat16_as_ushort(lo);
            }
        }
    }
}

// ---------------- edge kernel ----------------
__global__ void edge_kernel(const float* __restrict__ edges,
                            const int* __restrict__ senders,
                            const int* __restrict__ receivers,
                            float* __restrict__ out) {
    int e = blockIdx.x * blockDim.x + threadIdx.x;
    if (e >= NE) return;
    float e0 = edges[3 * e + 0];
    float e1 = edges[3 * e + 1];
    float e2 = edges[3 * e + 2];
    int s = senders[e];
    int r = receivers[e];
    float c0 = g_prep[0], c1 = g_prep[1], c2 = g_prep[2], d = g_prep[3];
    out[OUT_DECE + e] = fmaf(e0, c0, fmaf(e1, c1, fmaf(e2, c2, d)));
    float4* ps = &g_agg[s];
    float4* pr = &g_agg[NN + r];
    asm volatile("red.global.add.v4.f32 [%0], {%1, %2, %3, %4};"
                 :: "l"(ps), "f"(e0), "f"(e1), "f"(e2), "f"(1.0f) : "memory");
    asm volatile("red.global.add.v4.f32 [%0], {%1, %2, %3, %4};"
                 :: "l"(pr), "f"(e0), "f"(e1), "f"(e2), "f"(1.0f) : "memory");
}

// ---------------- smem: bias (256B) + packed k1..k4 slots (8KB each) ----------
#define SM_BIAS 0
#define SM_K1   256
#define SM_K2   (SM_K1 + 8192)
#define SM_K3   (SM_K2 + 8192)
#define SM_K4   (SM_K3 + 8192)
#define SM_TOTAL (SM_K4 + 8192)   /* ~33 KB */

// Build bf16 hi/lo A-fragments from PACKED fp32 pair fragments.
// Pair index p = nt*2 + rowhalf. a-frag j of k-tile kt <- pair 4*kt + j.
// hi = RZ-truncation via PRMT (one op packs both); lo = rn(x - hi).
__device__ __forceinline__ void mkfrag_p(const ull (&vp)[8],
                                         uint32_t (&ah)[2][4], uint32_t (&al)[2][4]) {
#pragma unroll
    for (int kt = 0; kt < 2; kt++)
#pragma unroll
        for (int j = 0; j < 4; j++) {
            float x, y;
            upk2(vp[4 * kt + j], x, y);
            uint32_t xb = __float_as_uint(x), yb = __float_as_uint(y);
            uint32_t hp;
            asm("prmt.b32 %0, %1, %2, 0x7632;" : "=r"(hp) : "r"(xb), "r"(yb));
            float r0 = x - __uint_as_float(xb & 0xFFFF0000u);
            float r1 = y - __uint_as_float(yb & 0xFFFF0000u);
            ah[kt][j] = hp;
            al[kt][j] = pkbf(r0, r1);
        }
}

// fully register-resident f-eval (R12 chain structure), packed I/O.
__device__ __forceinline__ void feval_reg(const ull (&vp)[8],
                                          const uint32_t (&bw)[2][4][4][2],
                                          const float2* __restrict__ sbias, int q,
                                          float (&kv)[4][4]) {
    uint32_t ah[2][4], al[2][4];
    mkfrag_p(vp, ah, al);
    float d[4][4];
#pragma unroll
    for (int nt = 0; nt < 4; nt++) {
        float2 bb = sbias[(0 * 4 + nt) * 4 + q];
        d[nt][0] = bb.x; d[nt][1] = bb.y; d[nt][2] = bb.x; d[nt][3] = bb.y;
        mma16816(d[nt], ah[0], bw[0][0][nt]);   // hi * Whi (k0)
        mma16816(d[nt], ah[1], bw[0][1][nt]);   // hi * Whi (k1)
        mma16816(d[nt], ah[0], bw[0][2][nt]);   // hi * Wlo (k0)
        mma16816(d[nt], ah[1], bw[0][3][nt]);   // hi * Wlo (k1)
        mma16816(d[nt], al[0], bw[0][0][nt]);   // lo * Whi (k0)
        mma16816(d[nt], al[1], bw[0][1][nt]);   // lo * Whi (k1)
    }
    // relu + repack to pairs
    ull dp[8];
#pragma unroll
    for (int p = 0; p < 8; p++) {
        int nt = p >> 1;
        int b = (p & 1) * 2;
        dp[p] = pk2(fmaxf(d[nt][b], 0.f), fmaxf(d[nt][b + 1], 0.f));
    }
    mkfrag_p(dp, ah, al);
#pragma unroll
    for (int nt = 0; nt < 4; nt++) {
        float2 bb = sbias[(1 * 4 + nt) * 4 + q];
        kv[nt][0] = bb.x; kv[nt][1] = bb.y; kv[nt][2] = bb.x; kv[nt][3] = bb.y;
        mma16816(kv[nt], ah[0], bw[1][0][nt]);
        mma16816(kv[nt], ah[1], bw[1][1][nt]);
        mma16816(kv[nt], ah[0], bw[1][2][nt]);
        mma16816(kv[nt], ah[1], bw[1][3][nt]);
        mma16816(kv[nt], al[0], bw[1][0][nt]);
        mma16816(kv[nt], al[1], bw[1][1][nt]);
    }
}

// RK stage frame — packed f32x2 state update (variadic: body may contain commas)
#define RK_FRAME(...)                                                         \
    {                                                                         \
        float kv[4][4];                                                       \
        feval_reg(vp, bw, sbias, q, kv);                                      \
        _Pragma("unroll")                                                     \
        for (int p = 0; p < 8; p++) {                                         \
            int nt = p >> 1;                                                  \
            int bb2 = (p & 1) * 2;                                            \
            int cg = p * 128 + t;                                             \
            ull kp = pk2(kv[nt][bb2], kv[nt][bb2 + 1]);                       \
            ull Y = ynp[p];                                                   \
            ull uu;                                                           \
            __VA_ARGS__                                                       \
            ynp[p] = Y;                                                       \
            vp[p] = uu;                                                       \
        }                                                                     \
    }

__global__ __launch_bounds__(128, 3)
void ode_kernel(const float* __restrict__ nodes, const float* __restrict__ gl,
                const float* __restrict__ encNW, const float* __restrict__ encNb,
                const float* __restrict__ encEW, const float* __restrict__ encEb,
                const float* __restrict__ b1g, const float* __restrict__ b2g,
                float* __restrict__ out) {
    extern __shared__ char sm[];
    int t = threadIdx.x;
    int w = t >> 5, lane = t & 31;
    int g = lane >> 2, q = lane & 3;
    int rb = w * 16;                    // warp owns 16 local rows
    int cbase = blockIdx.x * 64;        // CTA owns 64 nodes

    // ---- register-stationary B fragments ----
    uint32_t bw[2][4][4][2];
#pragma unroll
    for (int l = 0; l < 2; l++)
#pragma unroll
        for (int k8 = 0; k8 < 4; k8++)
#pragma unroll
            for (int nt = 0; nt < 4; nt++) {
                int n = nt * 8 + g;
                const unsigned short* src = g_wcat + l * 2048 + n * 64 + k8 * 16 + 2 * q;
                bw[l][k8][nt][0] = *(const uint32_t*)(src);
                bw[l][k8][nt][1] = *(const uint32_t*)(src + 8);
            }

    // ---- bias table in smem: [l(2)][nt(4)][q(4)] -> float2 ----
    float2* sbias = (float2*)(sm + SM_BIAS);
    if (t < 32) {
        int l = t >> 4;
        int nt = (t >> 2) & 3;
        int qq = t & 3;
        const float* b = l ? b2g : b1g;
        int c = nt * 8 + 2 * qq;
        sbias[t] = make_float2(__ldg(&b[c]), __ldg(&b[c + 1]));
    }

    // ---- encoder: threads 0..63 handle one node each ----
    float* scr = (float*)(sm + SM_K1);   // overlay: [col(32)][node(64)]
    if (t < 64) {
        int i0 = cbase + t;
        int i = (i0 < NN) ? i0 : (NN - 1);
        float2 nd = reinterpret_cast<const float2*>(nodes)[i];
        float4 sa = g_agg[i];
        float4 ra = g_agg[NN + i];
        float u0[32];
#pragma unroll
        for (int c = 0; c < 10; c++) {
            float wn0 = __ldg(&encNW[c]), wn1 = __ldg(&encNW[10 + c]), bn = __ldg(&encNb[c]);
            u0[c] = fmaf(nd.x, wn0, fmaf(nd.y, wn1, bn));
            float we0 = __ldg(&encEW[c]), we1 = __ldg(&encEW[10 + c]);
            float we2 = __ldg(&encEW[20 + c]), web = __ldg(&encEb[c]);
            u0[10 + c] = fmaf(sa.x, we0, fmaf(sa.y, we1, fmaf(sa.z, we2, sa.w * web)));
            u0[20 + c] = fmaf(ra.x, we0, fmaf(ra.y, we1, fmaf(ra.z, we2, ra.w * web)));
        }
        u0[30] = gl[0];
        u0[31] = gl[1];
#pragma unroll
        for (int c = 0; c < 32; c++) scr[c * 64 + t] = u0[c];
    }
    __syncthreads();

    ull ynp[8], vp[8];
#pragma unroll
    for (int p = 0; p < 8; p++) {
        int nt = p >> 1;
        int rh = p & 1;
        int row = rb + rh * 8 + g;
        int col = nt * 8 + 2 * q;
        ull val = pk2(scr[col * 64 + row], scr[(col + 1) * 64 + row]);
        ynp[p] = val;
        vp[p] = val;
    }
    __syncthreads();

    ull* k1p = (ull*)(sm + SM_K1);
    ull* k2p = (ull*)(sm + SM_K2);
    ull* k3p = (ull*)(sm + SM_K3);
    ull* k4p = (ull*)(sm + SM_K4);

#pragma unroll 1
    for (int st = 0; st < 10; ++st) {
        RK_FRAME(
            k1p[cg] = kp;
            Y = f2fma(kp, cpk(C_B1), Y);
            uu = f2fma(kp, cpk(C_R1), Y);
        )
        RK_FRAME(
            k2p[cg] = kp;
            ull tv = f2fma(k1p[cg], cpk(C_S31), Y);
            uu = f2fma(kp, cpk(C_R2), tv);
        )
        RK_FRAME(
            k3p[cg] = kp;
            Y = f2fma(kp, cpk(C_B3), Y);
            ull tv = f2fma(k1p[cg], cpk(C_S41), Y);
            tv = f2fma(k2p[cg], cpk(C_S42), tv);
            uu = f2fma(kp, cpk(C_R3), tv);
        )
        RK_FRAME(
            k4p[cg] = kp;
            Y = f2fma(kp, cpk(C_B4), Y);
            ull tv = f2fma(k1p[cg], cpk(C_S51), Y);
            tv = f2fma(k2p[cg], cpk(C_S52), tv);
            tv = f2fma(k3p[cg], cpk(C_S53), tv);
            uu = f2fma(kp, cpk(C_R4), tv);
        )
        RK_FRAME(
            Y = f2fma(kp, cpk(C_B5), Y);
            ull tv = f2fma(k1p[cg], cpk(C_S61), Y);
            tv = f2fma(k2p[cg], cpk(C_S62), tv);
            tv = f2fma(k3p[cg], cpk(C_S63), tv);
            tv = f2fma(k4p[cg], cpk(C_S64), tv);
            uu = f2fma(kp, cpk(C_R5), tv);
        )
        RK_FRAME(
            Y = f2fma(kp, cpk(C_B6), Y);
            uu = Y;
        )
    }

    // ---- decode + integrator epilogue (frag space, shfl row-reduce) ----
    float qc = __ldg(&g_prep[36]);
    float pdec[4][2];
#pragma unroll
    for (int nt = 0; nt < 4; nt++) {
        int c = nt * 8 + 2 * q;
        pdec[nt][0] = __ldg(&g_prep[4 + c]);
        pdec[nt][1] = __ldg(&g_prep[5 + c]);
    }
    float s1 = 0.f, s2 = 0.f;
#pragma unroll
    for (int nt = 0; nt < 4; nt++) {
        float a0, a1, b0, b1;
        upk2(ynp[nt * 2 + 0], a0, a1);
        upk2(ynp[nt * 2 + 1], b0, b1);
        s1 = fmaf(a0, pdec[nt][0], fmaf(a1, pdec[nt][1], s1));
        s2 = fmaf(b0, pdec[nt][0], fmaf(b1, pdec[nt][1], s2));
    }
    s1 += __shfl_xor_sync(0xFFFFFFFFu, s1, 1);
    s1 += __shfl_xor_sync(0xFFFFFFFFu, s1, 2);
    s2 += __shfl_xor_sync(0xFFFFFFFFu, s2, 1);
    s2 += __shfl_xor_sync(0xFFFFFFFFu, s2, 2);
    if (q == 0) {
        int iA = cbase + rb + g;
        int iB = iA + 8;
        if (iA < NN) {
            float2 n2 = reinterpret_cast<const float2*>(nodes)[iA];
            float dec = s1 + qc;
            out[iA] = dec;
            float vel = n2.y + dec;
            out[OUT_VEL + iA] = vel;
            out[OUT_POS + iA] = n2.x + vel;
        }
        if (iB < NN) {
            float2 n2 = reinterpret_cast<const float2*>(nodes)[iB];
            float dec = s2 + qc;
            out[iB] = dec;
            float vel = n2.y + dec;
            out[OUT_VEL + iB] = vel;
            out[OUT_POS + iB] = n2.x + vel;
        }
    }
}

extern "C" void kernel_launch(void* const* d_in, const int* in_sizes, int n_in,
                              void* d_out, int out_size) {
    const float* nodes     = (const float*)d_in[0];
    const float* edges     = (const float*)d_in[1];
    const int*   senders   = (const int*)d_in[2];
    const int*   receivers = (const int*)d_in[3];
    const float* globals_  = (const float*)d_in[4];
    const float* encNW     = (const float*)d_in[5];
    const float* encNb     = (const float*)d_in[6];
    const float* encEW     = (const float*)d_in[7];
    const float* encEb     = (const float*)d_in[8];
    const float* odeW1     = (const float*)d_in[9];
    const float* odeb1     = (const float*)d_in[10];
    const float* odeW2     = (const float*)d_in[11];
    const float* odeb2     = (const float*)d_in[12];
    const float* noW       = (const float*)d_in[13];
    const float* nob       = (const float*)d_in[14];
    const float* decNW     = (const float*)d_in[15];
    const float* decNb     = (const float*)d_in[16];
    const float* decEW     = (const float*)d_in[17];
    const float* decEb     = (const float*)d_in[18];
    float* out = (float*)d_out;

    cudaFuncSetAttribute(ode_kernel, cudaFuncAttributeMaxDynamicSharedMemorySize, SM_TOTAL);

    zero_prep_kernel<<<(2 * NN + 255) / 256, 256>>>(encEW, encEb, decEW, decEb,
                                                    noW, nob, decNW, decNb,
                                                    odeW1, odeW2);
    edge_kernel<<<(NE + 255) / 256, 256>>>(edges, senders, receivers, out);
    int nblk = (NN + 63) / 64;
    ode_kernel<<<nblk, 128, SM_TOTAL>>>(nodes, globals_, encNW, encNb, encEW, encEb,
                                        odeb1, odeb2, out);
}

// round 17
// speedup vs baseline: 1.0961x; 1.0010x over previous
#include <cuda_runtime.h>
#include <cuda_bf16.h>
#include <cstdint>

#define NN 100000
#define NE 1600000
#define OUT_DECE (NN)
#define OUT_POS  (NN + NE)
#define OUT_VEL  (NN + NE + NN)
#define NTILES ((NN + 63) / 64)
#define NCTAS 444

typedef unsigned long long ull;

// ---------------- device-global scratch ----------------
__device__ float4 g_agg[2 * NN];
__device__ float  g_prep[40];
// split bf16 weights: [l][n(32)][k(64)]: k<32 = hi(W[k][n]), k>=32 = lo residual
__device__ __align__(16) unsigned short g_wcat[2 * 32 * 64];

// ---------------- RK coefficients (H=0.1 absorbed, rebased on yn) ----------------
#define C_B1   ((float)(0.1 * (35.0/384.0)))
#define C_B3   ((float)(0.1 * (500.0/1113.0)))
#define C_B4   ((float)(0.1 * (125.0/192.0)))
#define C_B5   ((float)(0.1 * (-2187.0/6784.0)))
#define C_B6   ((float)(0.1 * (11.0/84.0)))
#define C_R1   ((float)(0.1 * (1.0/5.0 - 35.0/384.0)))
#define C_S31  ((float)(0.1 * (3.0/40.0 - 35.0/384.0)))
#define C_R2   ((float)(0.1 * (9.0/40.0)))
#define C_S41  ((float)(0.1 * (44.0/45.0 - 35.0/384.0)))
#define C_S42  ((float)(0.1 * (-56.0/15.0)))
#define C_R3   ((float)(0.1 * (32.0/9.0 - 500.0/1113.0)))
#define C_S51  ((float)(0.1 * (19372.0/6561.0 - 35.0/384.0)))
#define C_S52  ((float)(0.1 * (-25360.0/2187.0)))
#define C_S53  ((float)(0.1 * (64448.0/6561.0 - 500.0/1113.0)))
#define C_R4   ((float)(0.1 * (-212.0/729.0 - 125.0/192.0)))
#define C_S61  ((float)(0.1 * (9017.0/3168.0 - 35.0/384.0)))
#define C_S62  ((float)(0.1 * (-355.0/33.0)))
#define C_S63  ((float)(0.1 * (46732.0/5247.0 - 500.0/1113.0)))
#define C_S64  ((float)(0.1 * (49.0/176.0 - 125.0/192.0)))
#define C_R5   ((float)(0.1 * (-5103.0/18656.0 + 2187.0/6784.0)))

// ---------------- packed helpers ----------------
__device__ __forceinline__ ull pk2(float lo, float hi) {
    ull r;
    asm("mov.b64 %0, {%1, %2};" : "=l"(r) : "r"(__float_as_uint(lo)), "r"(__float_as_uint(hi)));
    return r;
}
__device__ __forceinline__ void upk2(ull v, float& lo, float& hi) {
    unsigned a, b;
    asm("mov.b64 {%0, %1}, %2;" : "=r"(a), "=r"(b) : "l"(v));
    lo = __uint_as_float(a); hi = __uint_as_float(b);
}
__device__ __forceinline__ ull f2fma(ull a, ull b, ull c) {
    ull d;
    asm("fma.rn.f32x2 %0, %1, %2, %3;" : "=l"(d) : "l"(a), "l"(b), "l"(c));
    return d;
}
__device__ __forceinline__ ull cpk(float x) {
    unsigned u = __float_as_uint(x);
    return (((ull)u) << 32) | (ull)u;
}
// pack (lo, hi) floats -> bf16x2 rn (first arg in low 16 bits)
__device__ __forceinline__ uint32_t pkbf(float lo, float hi) {
    uint32_t r;
    asm("cvt.rn.bf16x2.f32 %0, %1, %2;" : "=r"(r) : "f"(hi), "f"(lo));
    return r;
}
__device__ __forceinline__ void mma16816(float d[4], const uint32_t a[4], const uint32_t b[2]) {
    asm volatile("mma.sync.aligned.m16n8k16.row.col.f32.bf16.bf16.f32 "
                 "{%0,%1,%2,%3}, {%4,%5,%6,%7}, {%8,%9}, {%0,%1,%2,%3};"
                 : "+f"(d[0]), "+f"(d[1]), "+f"(d[2]), "+f"(d[3])
                 : "r"(a[0]), "r"(a[1]), "r"(a[2]), "r"(a[3]), "r"(b[0]), "r"(b[1]));
}

// ---------------- fused zero + precompute kernel ----------------
__global__ void zero_prep_kernel(const float* __restrict__ eW, const float* __restrict__ eb,
                                 const float* __restrict__ decEW, const float* __restrict__ decEb,
                                 const float* __restrict__ noW, const float* __restrict__ nob,
                                 const float* __restrict__ decNW, const float* __restrict__ decNb,
                                 const float* __restrict__ odeW1, const float* __restrict__ odeW2) {
    int i = blockIdx.x * blockDim.x + threadIdx.x;
    if (i < 2 * NN) g_agg[i] = make_float4(0.f, 0.f, 0.f, 0.f);
    if (blockIdx.x == 0) {
        int t = threadIdx.x;
        if (t < 3) {
            float s = 0.f;
            for (int c = 0; c < 10; c++) s += eW[t * 10 + c] * decEW[c];
            g_prep[t] = s;
        } else if (t == 3) {
            float s = decEb[0];
            for (int c = 0; c < 10; c++) s += eb[c] * decEW[c];
            g_prep[3] = s;
        } else if (t >= 4 && t < 36) {
            int j = t - 4;
            float s = 0.f;
            for (int c = 0; c < 10; c++) s += noW[j * 10 + c] * decNW[c];
            g_prep[t] = s;
        } else if (t == 36) {
            float s = decNb[0];
            for (int c = 0; c < 10; c++) s += nob[c] * decNW[c];
            g_prep[36] = s;
        }
        if (t >= 64 && t < 128) {
            int tt = t - 64;
            int l = tt >> 5, n = tt & 31;
            const float* W = l ? odeW2 : odeW1;
            unsigned short* dst = &g_wcat[l * 2048 + n * 64];
            for (int kk = 0; kk < 32; kk++) {
                float f = W[kk * 32 + n];
                __nv_bfloat16 hi = __float2bfloat16(f);
                __nv_bfloat16 lo = __float2bfloat16(f - __bfloat162float(hi));
                dst[kk]      = __bfloat16_as_ushort(hi);
                dst[32 + kk] = __bfloat16_as_ushort(lo);
            }
        }
    }
}

// ---------------- edge kernel ----------------
__global__ void edge_kernel(const float* __restrict__ edges,
                            const int* __restrict__ senders,
                            const int* __restrict__ receivers,
                            float* __restrict__ out) {
    int e = blockIdx.x * blockDim.x + threadIdx.x;
    if (e >= NE) return;
    float e0 = edges[3 * e + 0];
    float e1 = edges[3 * e + 1];
    float e2 = edges[3 * e + 2];
    int s = senders[e];
    int r = receivers[e];
    float c0 = g_prep[0], c1 = g_prep[1], c2 = g_prep[2], d = g_prep[3];
    out[OUT_DECE + e] = fmaf(e0, c0, fmaf(e1, c1, fmaf(e2, c2, d)));
    float4* ps = &g_agg[s];
    float4* pr = &g_agg[NN + r];
    asm volatile("red.global.add.v4.f32 [%0], {%1, %2, %3, %4};"
                 :: "l"(ps), "f"(e0), "f"(e1), "f"(e2), "f"(1.0f) : "memory");
    asm volatile("red.global.add.v4.f32 [%0], {%1, %2, %3, %4};"
                 :: "l"(pr), "f"(e0), "f"(e1), "f"(e2), "f"(1.0f) : "memory");
}

// ---------------- smem: bias (256B) + packed k1..k4 slots (8KB each) ----------
#define SM_BIAS 0
#define SM_K1   256
#define SM_K2   (SM_K1 + 8192)
#define SM_K3   (SM_K2 + 8192)
#define SM_K4   (SM_K3 + 8192)
#define SM_TOTAL (SM_K4 + 8192)   /* ~33 KB */

// Build bf16 hi/lo A-fragments from PACKED fp32 pair fragments.
__device__ __forceinline__ void mkfrag_p(const ull (&vp)[8],
                                         uint32_t (&ah)[2][4], uint32_t (&al)[2][4]) {
#pragma unroll
    for (int kt = 0; kt < 2; kt++)
#pragma unroll
        for (int j = 0; j < 4; j++) {
            float x, y;
            upk2(vp[4 * kt + j], x, y);
            uint32_t xb = __float_as_uint(x), yb = __float_as_uint(y);
            uint32_t hp;
            asm("prmt.b32 %0, %1, %2, 0x7632;" : "=r"(hp) : "r"(xb), "r"(yb));
            float r0 = x - __uint_as_float(xb & 0xFFFF0000u);
            float r1 = y - __uint_as_float(yb & 0xFFFF0000u);
            ah[kt][j] = hp;
            al[kt][j] = pkbf(r0, r1);
        }
}

// fully register-resident f-eval, packed I/O.
__device__ __forceinline__ void feval_reg(const ull (&vp)[8],
                                          const uint32_t (&bw)[2][4][4][2],
                                          const float2* __restrict__ sbias, int q,
                                          float (&kv)[4][4]) {
    uint32_t ah[2][4], al[2][4];
    mkfrag_p(vp, ah, al);
    float d[4][4];
#pragma unroll
    for (int nt = 0; nt < 4; nt++) {
        float2 bb = sbias[(0 * 4 + nt) * 4 + q];
        d[nt][0] = bb.x; d[nt][1] = bb.y; d[nt][2] = bb.x; d[nt][3] = bb.y;
        mma16816(d[nt], ah[0], bw[0][0][nt]);   // hi * Whi (k0)
        mma16816(d[nt], ah[1], bw[0][1][nt]);   // hi * Whi (k1)
        mma16816(d[nt], ah[0], bw[0][2][nt]);   // hi * Wlo (k0)
        mma16816(d[nt], ah[1], bw[0][3][nt]);   // hi * Wlo (k1)
        mma16816(d[nt], al[0], bw[0][0][nt]);   // lo * Whi (k0)
        mma16816(d[nt], al[1], bw[0][1][nt]);   // lo * Whi (k1)
    }
    ull dp[8];
#pragma unroll
    for (int p = 0; p < 8; p++) {
        int nt = p >> 1;
        int b = (p & 1) * 2;
        dp[p] = pk2(fmaxf(d[nt][b], 0.f), fmaxf(d[nt][b + 1], 0.f));
    }
    mkfrag_p(dp, ah, al);
#pragma unroll
    for (int nt = 0; nt < 4; nt++) {
        float2 bb = sbias[(1 * 4 + nt) * 4 + q];
        kv[nt][0] = bb.x; kv[nt][1] = bb.y; kv[nt][2] = bb.x; kv[nt][3] = bb.y;
        mma16816(kv[nt], ah[0], bw[1][0][nt]);
        mma16816(kv[nt], ah[1], bw[1][1][nt]);
        mma16816(kv[nt], ah[0], bw[1][2][nt]);
        mma16816(kv[nt], ah[1], bw[1][3][nt]);
        mma16816(kv[nt], al[0], bw[1][0][nt]);
        mma16816(kv[nt], al[1], bw[1][1][nt]);
    }
}

// RK stage frame — packed f32x2 state update (variadic: body may contain commas)
#define RK_FRAME(...)                                                         \
    {                                                                         \
        float kv[4][4];                                                       \
        feval_reg(vp, bw, sbias, q, kv);                                      \
        _Pragma("unroll")                                                     \
        for (int p = 0; p < 8; p++) {                                         \
            int nt = p >> 1;                                                  \
            int bb2 = (p & 1) * 2;                                            \
            int cg = p * 128 + t;                                             \
            ull kp = pk2(kv[nt][bb2], kv[nt][bb2 + 1]);                       \
            ull Y = ynp[p];                                                   \
            ull uu;                                                           \
            __VA_ARGS__                                                       \
            ynp[p] = Y;                                                       \
            vp[p] = uu;                                                       \
        }                                                                     \
    }

__global__ __launch_bounds__(128, 3)
void ode_kernel(const float* __restrict__ nodes, const float* __restrict__ gl,
                const float* __restrict__ encNW, const float* __restrict__ encNb,
                const float* __restrict__ encEW, const float* __restrict__ encEb,
                const float* __restrict__ b1g, const float* __restrict__ b2g,
                float* __restrict__ out) {
    extern __shared__ char sm[];
    int t = threadIdx.x;
    int w = t >> 5, lane = t & 31;
    int g = lane >> 2, q = lane & 3;
    int rb = w * 16;                    // warp owns 16 local rows

    // ---- register-stationary B fragments (loaded ONCE per CTA) ----
    uint32_t bw[2][4][4][2];
#pragma unroll
    for (int l = 0; l < 2; l++)
#pragma unroll
        for (int k8 = 0; k8 < 4; k8++)
#pragma unroll
            for (int nt = 0; nt < 4; nt++) {
                int n = nt * 8 + g;
                const unsigned short* src = g_wcat + l * 2048 + n * 64 + k8 * 16 + 2 * q;
                bw[l][k8][nt][0] = *(const uint32_t*)(src);
                bw[l][k8][nt][1] = *(const uint32_t*)(src + 8);
            }

    // ---- bias table in smem: [l(2)][nt(4)][q(4)] -> float2 ----
    float2* sbias = (float2*)(sm + SM_BIAS);
    if (t < 32) {
        int l = t >> 4;
        int nt = (t >> 2) & 3;
        int qq = t & 3;
        const float* b = l ? b2g : b1g;
        int c = nt * 8 + 2 * qq;
        sbias[t] = make_float2(__ldg(&b[c]), __ldg(&b[c + 1]));
    }

    // ---- decode vectors (once per CTA) ----
    float qc = __ldg(&g_prep[36]);
    float pdec[4][2];
#pragma unroll
    for (int nt = 0; nt < 4; nt++) {
        int c = nt * 8 + 2 * q;
        pdec[nt][0] = __ldg(&g_prep[4 + c]);
        pdec[nt][1] = __ldg(&g_prep[5 + c]);
    }

    float* scr = (float*)(sm + SM_K1);   // overlay: [col(32)][node(64)]
    ull* k1p = (ull*)(sm + SM_K1);
    ull* k2p = (ull*)(sm + SM_K2);
    ull* k3p = (ull*)(sm + SM_K3);
    ull* k4p = (ull*)(sm + SM_K4);

    // ---- persistent tile loop ----
#pragma unroll 1
    for (int tile = blockIdx.x; tile < NTILES; tile += NCTAS) {
        int cbase = tile * 64;
        __syncthreads();   // prior tile's k-slot reads done before scr overlay write

        // encoder: threads 0..63 handle one node each
        if (t < 64) {
            int i0 = cbase + t;
            int i = (i0 < NN) ? i0 : (NN - 1);
            float2 nd = reinterpret_cast<const float2*>(nodes)[i];
            float4 sa = g_agg[i];
            float4 ra = g_agg[NN + i];
            float u0[32];
#pragma unroll
            for (int c = 0; c < 10; c++) {
                float wn0 = __ldg(&encNW[c]), wn1 = __ldg(&encNW[10 + c]), bn = __ldg(&encNb[c]);
                u0[c] = fmaf(nd.x, wn0, fmaf(nd.y, wn1, bn));
                float we0 = __ldg(&encEW[c]), we1 = __ldg(&encEW[10 + c]);
                float we2 = __ldg(&encEW[20 + c]), web = __ldg(&encEb[c]);
                u0[10 + c] = fmaf(sa.x, we0, fmaf(sa.y, we1, fmaf(sa.z, we2, sa.w * web)));
                u0[20 + c] = fmaf(ra.x, we0, fmaf(ra.y, we1, fmaf(ra.z, we2, ra.w * web)));
            }
            u0[30] = gl[0];
            u0[31] = gl[1];
#pragma unroll
            for (int c = 0; c < 32; c++) scr[c * 64 + t] = u0[c];
        }
        __syncthreads();

        ull ynp[8], vp[8];
#pragma unroll
        for (int p = 0; p < 8; p++) {
            int nt = p >> 1;
            int rh = p & 1;
            int row = rb + rh * 8 + g;
            int col = nt * 8 + 2 * q;
            ull val = pk2(scr[col * 64 + row], scr[(col + 1) * 64 + row]);
            ynp[p] = val;
            vp[p] = val;
        }
        __syncthreads();   // frag gather complete before k-slot writes reuse SM_K1

#pragma unroll 1
        for (int st = 0; st < 10; ++st) {
            RK_FRAME(
                k1p[cg] = kp;
                Y = f2fma(kp, cpk(C_B1), Y);
                uu = f2fma(kp, cpk(C_R1), Y);
            )
            RK_FRAME(
                k2p[cg] = kp;
                ull tv = f2fma(k1p[cg], cpk(C_S31), Y);
                uu = f2fma(kp, cpk(C_R2), tv);
            )
            RK_FRAME(
                k3p[cg] = kp;
                Y = f2fma(kp, cpk(C_B3), Y);
                ull tv = f2fma(k1p[cg], cpk(C_S41), Y);
                tv = f2fma(k2p[cg], cpk(C_S42), tv);
                uu = f2fma(kp, cpk(C_R3), tv);
            )
            RK_FRAME(
                k4p[cg] = kp;
                Y = f2fma(kp, cpk(C_B4), Y);
                ull tv = f2fma(k1p[cg], cpk(C_S51), Y);
                tv = f2fma(k2p[cg], cpk(C_S52), tv);
                tv = f2fma(k3p[cg], cpk(C_S53), tv);
                uu = f2fma(kp, cpk(C_R4), tv);
            )
            RK_FRAME(
                Y = f2fma(kp, cpk(C_B5), Y);
                ull tv = f2fma(k1p[cg], cpk(C_S61), Y);
                tv = f2fma(k2p[cg], cpk(C_S62), tv);
                tv = f2fma(k3p[cg], cpk(C_S63), tv);
                tv = f2fma(k4p[cg], cpk(C_S64), tv);
                uu = f2fma(kp, cpk(C_R5), tv);
            )
            RK_FRAME(
                Y = f2fma(kp, cpk(C_B6), Y);
                uu = Y;
            )
        }

        // ---- decode + integrator epilogue ----
        float s1 = 0.f, s2 = 0.f;
#pragma unroll
        for (int nt = 0; nt < 4; nt++) {
            float a0, a1, b0, b1;
            upk2(ynp[nt * 2 + 0], a0, a1);
            upk2(ynp[nt * 2 + 1], b0, b1);
            s1 = fmaf(a0, pdec[nt][0], fmaf(a1, pdec[nt][1], s1));
            s2 = fmaf(b0, pdec[nt][0], fmaf(b1, pdec[nt][1], s2));
        }
        s1 += __shfl_xor_sync(0xFFFFFFFFu, s1, 1);
        s1 += __shfl_xor_sync(0xFFFFFFFFu, s1, 2);
        s2 += __shfl_xor_sync(0xFFFFFFFFu, s2, 1);
        s2 += __shfl_xor_sync(0xFFFFFFFFu, s2, 2);
        if (q == 0) {
            int iA = cbase + rb + g;
            int iB = iA + 8;
            if (iA < NN) {
                float2 n2 = reinterpret_cast<const float2*>(nodes)[iA];
                float dec = s1 + qc;
                out[iA] = dec;
                float vel = n2.y + dec;
                out[OUT_VEL + iA] = vel;
                out[OUT_POS + iA] = n2.x + vel;
            }
            if (iB < NN) {
                float2 n2 = reinterpret_cast<const float2*>(nodes)[iB];
                float dec = s2 + qc;
                out[iB] = dec;
                float vel = n2.y + dec;
                out[OUT_VEL + iB] = vel;
                out[OUT_POS + iB] = n2.x + vel;
            }
        }
    }
}

extern "C" void kernel_launch(void* const* d_in, const int* in_sizes, int n_in,
                              void* d_out, int out_size) {
    const float* nodes     = (const float*)d_in[0];
    const float* edges     = (const float*)d_in[1];
    const int*   senders   = (const int*)d_in[2];
    const int*   receivers = (const int*)d_in[3];
    const float* globals_  = (const float*)d_in[4];
    const float* encNW     = (const float*)d_in[5];
    const float* encNb     = (const float*)d_in[6];
    const float* encEW     = (const float*)d_in[7];
    const float* encEb     = (const float*)d_in[8];
    const float* odeW1     = (const float*)d_in[9];
    const float* odeb1     = (const float*)d_in[10];
    const float* odeW2     = (const float*)d_in[11];
    const float* odeb2     = (const float*)d_in[12];
    const float* noW       = (const float*)d_in[13];
    const float* nob       = (const float*)d_in[14];
    const float* decNW     = (const float*)d_in[15];
    const float* decNb     = (const float*)d_in[16];
    const float* decEW     = (const float*)d_in[17];
    const float* decEb     = (const float*)d_in[18];
    float* out = (float*)d_out;

    cudaFuncSetAttribute(ode_kernel, cudaFuncAttributeMaxDynamicSharedMemorySize, SM_TOTAL);

    zero_prep_kernel<<<(2 * NN + 255) / 256, 256>>>(encEW, encEb, decEW, decEb,
                                                    noW, nob, decNW, decNb,
                                                    odeW1, odeW2);
    edge_kernel<<<(NE + 255) / 256, 256>>>(edges, senders, receivers, out);
    ode_kernel<<<NCTAS, 128, SM_TOTAL>>>(nodes, globals_, encNW, encNb, encEW, encEb,
                                         odeb1, odeb2, out);
}